// round 15
// baseline (speedup 1.0000x reference)
#include <cuda_runtime.h>
#include <cuda_bf16.h>
#include <cstdint>
#include <cstddef>

#define B_ 4
#define T_ 2048
#define D_ 2048
#define H_ 16
#define M_ 8192              // B*T
#define NP 10368             // fused projection cols: q|k|v|a|b(pad)|g
#define CQ 0
#define CK 2048
#define CV 4096
#define CA 6144
#define CB 8192              // 16 real cols, padded to 128
#define CG 8320              // 2048 cols, tail of the matrix

// ---------------- scratch (static device globals; no allocation) ----------------
__device__ __nv_bfloat16 g_xh[(size_t)M_ * D_];
__device__ __nv_bfloat16 g_xl[(size_t)M_ * D_];
__device__ __nv_bfloat16 g_Wh[(size_t)NP * D_];
__device__ __nv_bfloat16 g_Wl[(size_t)NP * D_];
__device__ float         g_P [(size_t)M_ * NP];
__device__ float         g_qkv[(size_t)M_ * 6144];
__device__ float         g_decay[(size_t)M_ * 2048];
__device__ float         g_vT[(size_t)64 * 128 * 2048];   // [bh][j][t]
__device__ float         g_betaT[(size_t)64 * 2048];      // [bh][t]
__device__ float         g_oscan[(size_t)M_ * 2048];
__device__ __nv_bfloat16 g_yh[(size_t)M_ * 2048];
__device__ __nv_bfloat16 g_yl[(size_t)M_ * 2048];
__device__ __nv_bfloat16 g_W2h[(size_t)D_ * 2048];
__device__ __nv_bfloat16 g_W2l[(size_t)D_ * 2048];

// ---------------- small helpers ----------------
__device__ __forceinline__ float sigf(float z) { return 1.f / (1.f + __expf(-z)); }

__device__ __forceinline__ void ldm4(uint32_t* r, uint32_t addr) {
    asm volatile("ldmatrix.sync.aligned.m8n8.x4.shared.b16 {%0,%1,%2,%3}, [%4];"
                 : "=r"(r[0]), "=r"(r[1]), "=r"(r[2]), "=r"(r[3]) : "r"(addr));
}
__device__ __forceinline__ void mma16816(float* c, const uint32_t* a, const uint32_t* b) {
    asm volatile("mma.sync.aligned.m16n8k16.row.col.f32.bf16.bf16.f32 "
                 "{%0,%1,%2,%3},{%4,%5,%6,%7},{%8,%9},{%0,%1,%2,%3};"
                 : "+f"(c[0]), "+f"(c[1]), "+f"(c[2]), "+f"(c[3])
                 : "r"(a[0]), "r"(a[1]), "r"(a[2]), "r"(a[3]), "r"(b[0]), "r"(b[1]));
}
__device__ __forceinline__ void cpa16(uint32_t saddr, const void* gaddr) {
    asm volatile("cp.async.cg.shared.global [%0], [%1], 16;" :: "r"(saddr), "l"(gaddr));
}
__device__ __forceinline__ void cpcommit() { asm volatile("cp.async.commit_group;"); }
template <int N> __device__ __forceinline__ void cpwait() {
    asm volatile("cp.async.wait_group %0;" :: "n"(N));
}

// ---- packed f32x2 ----
__device__ __forceinline__ unsigned long long f2pack(float lo, float hi) {
    unsigned long long r;
    asm("mov.b64 %0, {%1, %2};" : "=l"(r) : "f"(lo), "f"(hi));
    return r;
}
__device__ __forceinline__ unsigned long long f2fma(unsigned long long a, unsigned long long b, unsigned long long c) {
    unsigned long long r;
    asm("fma.rn.f32x2 %0, %1, %2, %3;" : "=l"(r) : "l"(a), "l"(b), "l"(c));
    return r;
}
__device__ __forceinline__ unsigned long long f2mul(unsigned long long a, unsigned long long b) {
    unsigned long long r;
    asm("mul.rn.f32x2 %0, %1, %2;" : "=l"(r) : "l"(a), "l"(b));
    return r;
}
__device__ __forceinline__ unsigned long long f2add(unsigned long long a, unsigned long long b) {
    unsigned long long r;
    asm("add.rn.f32x2 %0, %1, %2;" : "=l"(r) : "l"(a), "l"(b));
    return r;
}
__device__ __forceinline__ float f2lo(unsigned long long x) { return __uint_as_float((uint32_t)x); }
__device__ __forceinline__ float f2hi(unsigned long long x) { return __uint_as_float((uint32_t)(x >> 32)); }

// ---------------- split fp32 -> (hi, lo) bf16, float4-vectorized ----------------
__global__ void split_f32_v4(const float* __restrict__ src, __nv_bfloat16* __restrict__ hi,
                             __nv_bfloat16* __restrict__ lo, size_t n4) {
    size_t i = (size_t)blockIdx.x * blockDim.x + threadIdx.x;
    if (i >= n4) return;
    float4 v = ((const float4*)src)[i];
    __nv_bfloat16 hx = __float2bfloat16(v.x), hy = __float2bfloat16(v.y);
    __nv_bfloat16 hz = __float2bfloat16(v.z), hw = __float2bfloat16(v.w);
    __nv_bfloat162* hp = (__nv_bfloat162*)hi;
    __nv_bfloat162* lp = (__nv_bfloat162*)lo;
    hp[i * 2]     = __nv_bfloat162(hx, hy);
    hp[i * 2 + 1] = __nv_bfloat162(hz, hw);
    lp[i * 2]     = __nv_bfloat162(__float2bfloat16(v.x - __bfloat162float(hx)),
                                   __float2bfloat16(v.y - __bfloat162float(hy)));
    lp[i * 2 + 1] = __nv_bfloat162(__float2bfloat16(v.z - __bfloat162float(hz)),
                                   __float2bfloat16(v.w - __bfloat162float(hw)));
}

// ---------------- build fused+padded weight matrix, layout q|k|v|a|b|g ----------------
__global__ void build_wcat(const float* __restrict__ Wq, const float* __restrict__ Wk,
                           const float* __restrict__ Wv, const float* __restrict__ Wa,
                           const float* __restrict__ Wg, const float* __restrict__ Wb) {
    size_t i = (size_t)blockIdx.x * blockDim.x + threadIdx.x;   // over float4s
    if (i >= (size_t)NP * D_ / 4) return;
    int n = (int)(i / (D_ / 4));
    int d4 = (int)(i % (D_ / 4));
    float4 v = make_float4(0.f, 0.f, 0.f, 0.f);
    if      (n < 2048)  v = ((const float4*)Wq)[(size_t)n * (D_ / 4) + d4];
    else if (n < 4096)  v = ((const float4*)Wk)[(size_t)(n - 2048) * (D_ / 4) + d4];
    else if (n < 6144)  v = ((const float4*)Wv)[(size_t)(n - 4096) * (D_ / 4) + d4];
    else if (n < 8192)  v = ((const float4*)Wa)[(size_t)(n - 6144) * (D_ / 4) + d4];
    else if (n < 8208)  v = ((const float4*)Wb)[(size_t)(n - 8192) * (D_ / 4) + d4];
    else if (n >= 8320) v = ((const float4*)Wg)[(size_t)(n - 8320) * (D_ / 4) + d4];
    __nv_bfloat16 hx = __float2bfloat16(v.x), hy = __float2bfloat16(v.y);
    __nv_bfloat16 hz = __float2bfloat16(v.z), hw = __float2bfloat16(v.w);
    __nv_bfloat162* hp = (__nv_bfloat162*)g_Wh;
    __nv_bfloat162* lp = (__nv_bfloat162*)g_Wl;
    hp[i * 2]     = __nv_bfloat162(hx, hy);
    hp[i * 2 + 1] = __nv_bfloat162(hz, hw);
    lp[i * 2]     = __nv_bfloat162(__float2bfloat16(v.x - __bfloat162float(hx)),
                                   __float2bfloat16(v.y - __bfloat162float(hy)));
    lp[i * 2 + 1] = __nv_bfloat162(__float2bfloat16(v.z - __bfloat162float(hz)),
                                   __float2bfloat16(v.w - __bfloat162float(hw)));
}

// ---------------- split-bf16 GEMM (measured-best config) + N-tile offset ----------------
__device__ __forceinline__ void gemm_issue_stage(
    uint32_t smem, int stage, int tid,
    const __nv_bfloat16* Ah, const __nv_bfloat16* Al,
    const __nv_bfloat16* Bh, const __nv_bfloat16* Bl,
    int m0, int n0, int k0, int Kd)
{
#pragma unroll
    for (int i = 0; i < 2; i++) {
        int idx = tid + i * 256;
        int row = idx >> 2, ch = idx & 3;
        int pch = ch ^ ((row >> 1) & 3);
        uint32_t so = smem + stage * 32768 + row * 64 + pch * 16;
        size_t ga = (size_t)(m0 + row) * Kd + k0 + ch * 8;
        size_t gb = (size_t)(n0 + row) * Kd + k0 + ch * 8;
        cpa16(so,         Ah + ga);
        cpa16(so + 8192,  Al + ga);
        cpa16(so + 16384, Bh + gb);
        cpa16(so + 24576, Bl + gb);
    }
}

__global__ void __launch_bounds__(256, 2) gemm_split(
    const __nv_bfloat16* __restrict__ Ah, const __nv_bfloat16* __restrict__ Al,
    const __nv_bfloat16* __restrict__ Bh, const __nv_bfloat16* __restrict__ Bl,
    float* __restrict__ C, int M, int N, int Kd, int ntile0)
{
    extern __shared__ char sm_[];
    uint32_t smem = (uint32_t)__cvta_generic_to_shared(sm_);
    int tid = threadIdx.x;
    int warp = tid >> 5, lane = tid & 31;
    int wm = warp >> 2, wn = warp & 3;
    int m0 = blockIdx.y * 128, n0 = (blockIdx.x + ntile0) * 128;

    float acc[4][4][4];
#pragma unroll
    for (int a = 0; a < 4; a++)
#pragma unroll
        for (int b = 0; b < 4; b++)
#pragma unroll
            for (int c = 0; c < 4; c++) acc[a][b][c] = 0.f;

    int nkt = Kd >> 5;
    gemm_issue_stage(smem, 0, tid, Ah, Al, Bh, Bl, m0, n0, 0, Kd);
    cpcommit();

    for (int kt = 0; kt < nkt; kt++) {
        if (kt + 1 < nkt) {
            gemm_issue_stage(smem, (kt + 1) & 1, tid, Ah, Al, Bh, Bl, m0, n0, (kt + 1) * 32, Kd);
            cpcommit();
            cpwait<1>();
        } else {
            cpwait<0>();
        }
        __syncthreads();

        uint32_t base = smem + (kt & 1) * 32768;
#pragma unroll
        for (int k16 = 0; k16 < 2; k16++) {
            uint32_t a_h[4][4], a_l[4][4];
#pragma unroll
            for (int ms = 0; ms < 4; ms++) {
                int r = wm * 64 + ms * 16 + (lane & 15);
                int ch = k16 * 2 + (lane >> 4);
                int pch = ch ^ ((r >> 1) & 3);
                uint32_t ad = base + r * 64 + pch * 16;
                ldm4(a_h[ms], ad);
                ldm4(a_l[ms], ad + 8192);
            }
            uint32_t b_h[2][4], b_l[2][4];
#pragma unroll
            for (int ns = 0; ns < 2; ns++) {
                int r = wn * 32 + ns * 16 + (lane & 7) + ((lane >> 4) << 3);
                int ch = k16 * 2 + ((lane >> 3) & 1);
                int pch = ch ^ ((r >> 1) & 3);
                uint32_t ad = base + 16384 + r * 64 + pch * 16;
                ldm4(b_h[ns], ad);
                ldm4(b_l[ns], ad + 8192);
            }
#pragma unroll
            for (int ms = 0; ms < 4; ms++)
#pragma unroll
                for (int j = 0; j < 4; j++) {
                    const uint32_t* bhp = &b_h[j >> 1][(j & 1) * 2];
                    const uint32_t* blp = &b_l[j >> 1][(j & 1) * 2];
                    mma16816(acc[ms][j], a_h[ms], bhp);   // hi*hi
                    mma16816(acc[ms][j], a_h[ms], blp);   // hi*lo
                    mma16816(acc[ms][j], a_l[ms], bhp);   // lo*hi
                }
        }
        __syncthreads();
    }

#pragma unroll
    for (int ms = 0; ms < 4; ms++)
#pragma unroll
        for (int j = 0; j < 4; j++) {
            int row = m0 + wm * 64 + ms * 16 + (lane >> 2);
            int col = n0 + wn * 32 + j * 8 + (lane & 3) * 2;
            float2 v0; v0.x = acc[ms][j][0]; v0.y = acc[ms][j][1];
            float2 v1; v1.x = acc[ms][j][2]; v1.y = acc[ms][j][3];
            *(float2*)(C + (size_t)row * N + col)       = v0;
            *(float2*)(C + (size_t)(row + 8) * N + col) = v1;
        }
}

// ---------------- depthwise causal conv (K=4) + SiLU, 4 channels/thread ----------------
__global__ void conv_silu_v4(const float* __restrict__ cqw, const float* __restrict__ cqb,
                             const float* __restrict__ ckw, const float* __restrict__ ckb,
                             const float* __restrict__ cvw, const float* __restrict__ cvb) {
    size_t i = (size_t)blockIdx.x * blockDim.x + threadIdx.x;
    if (i >= (size_t)M_ * 1536) return;
    int c4 = (int)(i % 1536);
    size_t r = i / 1536;
    int t = (int)(r & (T_ - 1));
    int c = c4 * 4;

    const float* w;
    const float* bias;
    if (c < 2048)      { w = cqw + (size_t)c * 4;          bias = cqb + c; }
    else if (c < 4096) { w = ckw + (size_t)(c - 2048) * 4; bias = ckb + (c - 2048); }
    else               { w = cvw + (size_t)(c - 4096) * 4; bias = cvb + (c - 4096); }

    const float* src = g_P + r * (size_t)NP + c;
    float4 t0 = (t >= 3) ? *(const float4*)(src - 3 * NP) : make_float4(0.f, 0.f, 0.f, 0.f);
    float4 t1 = (t >= 2) ? *(const float4*)(src - 2 * NP) : make_float4(0.f, 0.f, 0.f, 0.f);
    float4 t2 = (t >= 1) ? *(const float4*)(src - 1 * NP) : make_float4(0.f, 0.f, 0.f, 0.f);
    float4 t3 = *(const float4*)(src);

    float4 w0 = *(const float4*)(w);
    float4 w1 = *(const float4*)(w + 4);
    float4 w2 = *(const float4*)(w + 8);
    float4 w3 = *(const float4*)(w + 12);
    float4 bi = *(const float4*)(bias);

    float4 out;
    {
        float a = bi.x + w0.x * t0.x + w0.y * t1.x + w0.z * t2.x + w0.w * t3.x;
        out.x = a * sigf(a);
        float b = bi.y + w1.x * t0.y + w1.y * t1.y + w1.z * t2.y + w1.w * t3.y;
        out.y = b * sigf(b);
        float cc = bi.z + w2.x * t0.z + w2.y * t1.z + w2.z * t2.z + w2.w * t3.z;
        out.z = cc * sigf(cc);
        float d = bi.w + w3.x * t0.w + w3.y * t1.w + w3.z * t2.w + w3.w * t3.w;
        out.w = d * sigf(d);
    }
    *(float4*)(g_qkv + r * 6144 + c) = out;
}

// ---------------- tiled transpose of v ----------------
__global__ void transpose_v() {
    __shared__ float tile[32][33];
    int bh = blockIdx.x;
    int b = bh >> 4, h = bh & 15;
    int j0 = blockIdx.y * 32;
    int t0 = blockIdx.z * 32;
    int tx = threadIdx.x, ty = threadIdx.y;   // 32 x 8

    const float* src = g_qkv + ((size_t)b * T_ + t0) * 6144 + CV + h * 128 + j0;
#pragma unroll
    for (int p = 0; p < 4; p++) {
        int tt = ty + p * 8;
        tile[tt][tx] = src[(size_t)tt * 6144 + tx];
    }
    __syncthreads();
    float* dst = g_vT + (((size_t)bh) * 128 + j0) * 2048 + t0;
#pragma unroll
    for (int p = 0; p < 4; p++) {
        int jj = ty + p * 8;
        dst[(size_t)jj * 2048 + tx] = tile[tx][jj];
    }
}

// ---------------- decay / beta ----------------
__global__ void decay_kernel_v4(const float* __restrict__ ba) {
    size_t i = (size_t)blockIdx.x * blockDim.x + threadIdx.x;
    if (i >= (size_t)M_ * 512) return;
    int c4 = (int)(i % 512);
    size_t r = i / 512;
    int c = c4 * 4;
    float4 p = *(const float4*)(g_P + r * (size_t)NP + CA + c);
    float4 bv = *(const float4*)(ba + c);
    float4 o;
    o.x = fmaxf(sigf(p.x + bv.x), 1e-6f);
    o.y = fmaxf(sigf(p.y + bv.y), 1e-6f);
    o.z = fmaxf(sigf(p.z + bv.z), 1e-6f);
    o.w = fmaxf(sigf(p.w + bv.w), 1e-6f);
    *(float4*)(g_decay + r * 2048 + c) = o;
}

__global__ void beta_kernel(const float* __restrict__ bb) {
    size_t i = (size_t)blockIdx.x * blockDim.x + threadIdx.x;
    if (i >= (size_t)M_ * H_) return;
    int h = (int)(i % H_);
    size_t r = i / H_;
    int b = (int)(r >> 11), t = (int)(r & (T_ - 1));
    g_betaT[((size_t)(b * 16 + h)) * 2048 + t] = sigf(g_P[r * (size_t)NP + CB + h] + bb[h]);
}

// ---------------- gated delta-rule scan (measured best) ----------------
__device__ __forceinline__ unsigned long long red32p(unsigned long long x) {
    x = f2add(x, __shfl_xor_sync(0xffffffffu, x, 1));
    x = f2add(x, __shfl_xor_sync(0xffffffffu, x, 2));
    x = f2add(x, __shfl_xor_sync(0xffffffffu, x, 4));
    x = f2add(x, __shfl_xor_sync(0xffffffffu, x, 8));
    x = f2add(x, __shfl_xor_sync(0xffffffffu, x, 16));
    return x;
}
__device__ __forceinline__ float f4c(const float4& v, int u) {
    return u == 0 ? v.x : (u == 1 ? v.y : (u == 2 ? v.z : v.w));
}

__global__ void __launch_bounds__(128, 7) kda_scan() {
    int warp = threadIdx.x >> 5, lane = threadIdx.x & 31;
    int bh = blockIdx.x;
    int b = bh >> 4, h = bh & 15;
    int wj = blockIdx.y * 4 + warp;
    int j0 = wj * 2;
    size_t rbase = (size_t)b * T_;

    const float* kb  = g_qkv   + rbase * 6144 + CK + h * 128 + lane * 4;
    const float* qb  = g_qkv   + rbase * 6144 + CQ + h * 128 + lane * 4;
    const float* db  = g_decay + rbase * 2048 + h * 128 + lane * 4;
    const float* v0p = g_vT + (((size_t)bh) * 128 + j0) * 2048;
    const float* v1p = v0p + 2048;
    const float* btp = g_betaT + (size_t)bh * 2048;
    float* ob = g_oscan + rbase * 2048 + h * 128 + j0;

    unsigned long long sp0 = 0ull, sp1 = 0ull, sp2 = 0ull, sp3 = 0ull;
    const float scale = 0.08838834764831845f;

    float4 k4 = *(const float4*)(kb);
    float4 d4 = *(const float4*)(db);
    float4 q4 = *(const float4*)(qb);

    for (int tg = 0; tg < T_; tg += 4) {
        float4 vA  = *(const float4*)(v0p + tg);
        float4 vB  = *(const float4*)(v1p + tg);
        float4 bt4 = *(const float4*)(btp + tg);
#pragma unroll
        for (int u = 0; u < 4; u++) {
            int t = tg + u;
            int tn = (t + 1 < T_) ? t + 1 : t;

            unsigned long long kp0 = f2pack(k4.x, k4.x), kp1 = f2pack(k4.y, k4.y);
            unsigned long long kp2 = f2pack(k4.z, k4.z), kp3 = f2pack(k4.w, k4.w);
            unsigned long long dp0 = f2pack(d4.x, d4.x), dp1 = f2pack(d4.y, d4.y);
            unsigned long long dp2 = f2pack(d4.z, d4.z), dp3 = f2pack(d4.w, d4.w);

            sp0 = f2mul(sp0, dp0); sp1 = f2mul(sp1, dp1);
            sp2 = f2mul(sp2, dp2); sp3 = f2mul(sp3, dp3);
            float4 nd = *(const float4*)(db + (size_t)tn * 2048);

            unsigned long long acc = f2mul(kp0, sp0);
            acc = f2fma(kp1, sp1, acc);
            acc = f2fma(kp2, sp2, acc);
            acc = f2fma(kp3, sp3, acc);
            acc = red32p(acc);
            float p0 = f2lo(acc), p1 = f2hi(acc);

            float btc = f4c(bt4, u);
            float be0 = btc * (f4c(vA, u) - p0);
            float be1 = btc * (f4c(vB, u) - p1);
            unsigned long long bep = f2pack(be0, be1);

            sp0 = f2fma(bep, kp0, sp0); sp1 = f2fma(bep, kp1, sp1);
            sp2 = f2fma(bep, kp2, sp2); sp3 = f2fma(bep, kp3, sp3);
            float4 nk = *(const float4*)(kb + (size_t)tn * 6144);

            unsigned long long qp0 = f2pack(q4.x, q4.x), qp1 = f2pack(q4.y, q4.y);
            unsigned long long qp2 = f2pack(q4.z, q4.z), qp3 = f2pack(q4.w, q4.w);
            unsigned long long oacc = f2mul(qp0, sp0);
            oacc = f2fma(qp1, sp1, oacc);
            oacc = f2fma(qp2, sp2, oacc);
            oacc = f2fma(qp3, sp3, oacc);
            float4 nq = *(const float4*)(qb + (size_t)tn * 6144);
            oacc = red32p(oacc);

            if (lane < 2) ob[(size_t)t * 2048 + lane] =
                (lane ? f2hi(oacc) : f2lo(oacc)) * scale;

            k4 = nk; d4 = nd; q4 = nq;
        }
    }
}

// ---------------- per-head LayerNorm + sigmoid gate + split to bf16 hi/lo ----------------
__global__ void ln_gate(const float* __restrict__ ln_w, const float* __restrict__ ln_b) {
    int gwarp = (int)(((size_t)blockIdx.x * blockDim.x + threadIdx.x) >> 5);
    int lane = threadIdx.x & 31;
    if (gwarp >= M_ * H_) return;
    int h = gwarp & 15;
    size_t r = (size_t)(gwarp >> 4);

    const float* obp = g_oscan + r * 2048 + h * 128;
    float4 o4 = *(const float4*)(obp + lane * 4);
    float sum = o4.x + o4.y + o4.z + o4.w;
#pragma unroll
    for (int off = 16; off; off >>= 1) sum += __shfl_xor_sync(0xffffffffu, sum, off);
    float mu = sum * (1.f / 128.f);
    float dx = o4.x - mu, dy = o4.y - mu, dz = o4.z - mu, dw = o4.w - mu;
    float sq = dx * dx + dy * dy + dz * dz + dw * dw;
#pragma unroll
    for (int off = 16; off; off >>= 1) sq += __shfl_xor_sync(0xffffffffu, sq, off);
    float rs = rsqrtf(sq * (1.f / 128.f) + 1e-5f);

    float vals[4] = {dx, dy, dz, dw};
#pragma unroll
    for (int e = 0; e < 4; e++) {
        int jj = lane * 4 + e;
        float y = vals[e] * rs * ln_w[jj] + ln_b[jj];
        float gate = sigf(g_P[r * (size_t)NP + CG + h * 128 + jj]);
        y *= gate;
        size_t idx = r * 2048 + h * 128 + jj;
        __nv_bfloat16 hh = __float2bfloat16(y);
        g_yh[idx] = hh;
        g_yl[idx] = __float2bfloat16(y - __bfloat162float(hh));
    }
}

// ---------------- launch ----------------
extern "C" void kernel_launch(void* const* d_in, const int* in_sizes, int n_in,
                              void* d_out, int out_size) {
    const float* x    = (const float*)d_in[0];
    const float* Wq   = (const float*)d_in[1];
    const float* Wk   = (const float*)d_in[2];
    const float* Wv   = (const float*)d_in[3];
    const float* Wa   = (const float*)d_in[4];
    const float* ba   = (const float*)d_in[5];
    const float* Wb   = (const float*)d_in[6];
    const float* bb   = (const float*)d_in[7];
    const float* Wg   = (const float*)d_in[8];
    const float* Wo   = (const float*)d_in[9];
    const float* cqw  = (const float*)d_in[10];
    const float* cqb  = (const float*)d_in[11];
    const float* ckw  = (const float*)d_in[12];
    const float* ckb  = (const float*)d_in[13];
    const float* cvw  = (const float*)d_in[14];
    const float* cvb  = (const float*)d_in[15];
    const float* ln_w = (const float*)d_in[16];
    const float* ln_b = (const float*)d_in[17];
    float* out = (float*)d_out;

    static __nv_bfloat16 *pxh = nullptr, *pxl, *pWh, *pWl, *pyh, *pyl, *pW2h, *pW2l;
    static float *pP;
    static cudaStream_t s1;
    static cudaEvent_t ev_a, ev_join;
    if (!pxh) {
        cudaGetSymbolAddress((void**)&pxh, g_xh);
        cudaGetSymbolAddress((void**)&pxl, g_xl);
        cudaGetSymbolAddress((void**)&pWh, g_Wh);
        cudaGetSymbolAddress((void**)&pWl, g_Wl);
        cudaGetSymbolAddress((void**)&pP,  g_P);
        cudaGetSymbolAddress((void**)&pyh, g_yh);
        cudaGetSymbolAddress((void**)&pyl, g_yl);
        cudaGetSymbolAddress((void**)&pW2h, g_W2h);
        cudaGetSymbolAddress((void**)&pW2l, g_W2l);
        cudaFuncSetAttribute(gemm_split, cudaFuncAttributeMaxDynamicSharedMemorySize, 65536);
        cudaStreamCreateWithFlags(&s1, cudaStreamNonBlocking);
        cudaEventCreateWithFlags(&ev_a, cudaEventDisableTiming);
        cudaEventCreateWithFlags(&ev_join, cudaEventDisableTiming);
    }

    const int TPB = 256;

    // 1) split inputs to bf16 hi/lo (vectorized)
    split_f32_v4<<<(int)(((size_t)M_ * D_ / 4 + TPB - 1) / TPB), TPB>>>(x, pxh, pxl, (size_t)M_ * D_ / 4);
    build_wcat<<<(int)(((size_t)NP * D_ / 4 + TPB - 1) / TPB), TPB>>>(Wq, Wk, Wv, Wa, Wg, Wb);
    split_f32_v4<<<(int)(((size_t)D_ * 2048 / 4 + TPB - 1) / TPB), TPB>>>(Wo, pW2h, pW2l, (size_t)D_ * 2048 / 4);

    // 2a) main: projection GEMM for q|k|v|a|b cols (65 tiles)
    gemm_split<<<dim3(65, M_ / 128), 256, 65536>>>(pxh, pxl, pWh, pWl, pP, M_, NP, D_, 0);
    cudaEventRecord(ev_a, 0);

    // 2b) side: g-column GEMM starts only AFTER gemm1a, so it overlaps the
    // conv/transpose/decay/beta/scan phase (which has idle tensor + issue slots).
    cudaStreamWaitEvent(s1, ev_a, 0);
    gemm_split<<<dim3(16, M_ / 128), 256, 65536, s1>>>(pxh, pxl, pWh, pWl, pP, M_, NP, D_, 65);
    cudaEventRecord(ev_join, s1);

    // 3) conv + transpose + decay + beta (main stream; overlaps 2b)
    conv_silu_v4<<<(int)(((size_t)M_ * 1536 + TPB - 1) / TPB), TPB>>>(cqw, cqb, ckw, ckb, cvw, cvb);
    transpose_v<<<dim3(64, 4, 64), dim3(32, 8)>>>();
    decay_kernel_v4<<<(int)(((size_t)M_ * 512 + TPB - 1) / TPB), TPB>>>(ba);
    beta_kernel<<<(int)(((size_t)M_ * H_ + TPB - 1) / TPB), TPB>>>(bb);

    // 5) gated delta-rule scan (overlaps 2b)
    kda_scan<<<dim3(B_ * H_, 16), 128>>>();

    // join: ln_gate needs the g columns from 2b
    cudaStreamWaitEvent(0, ev_join, 0);

    // 6) LayerNorm + gate + bf16 split
    ln_gate<<<M_ * H_ / 8, 256>>>(ln_w, ln_b);

    // 7) output projection: out = y @ Wo^T   (8192 x 2048 x 2048)
    gemm_split<<<dim3(16, M_ / 128), 256, 65536>>>(pyh, pyl, pW2h, pW2l, out, M_, 2048, D_, 0);
}

// round 16
// speedup vs baseline: 1.0169x; 1.0169x over previous
#include <cuda_runtime.h>
#include <cuda_bf16.h>
#include <cstdint>
#include <cstddef>

#define B_ 4
#define T_ 2048
#define D_ 2048
#define H_ 16
#define M_ 8192              // B*T
#define NP 10368             // fused projection cols: q|k|v|a|b(pad)|g
#define CQ 0
#define CK 2048
#define CV 4096
#define CA 6144
#define CB 8192              // 16 real cols, padded to 128
#define CG 8320              // 2048 cols, tail of the matrix

// ---------------- scratch (static device globals; no allocation) ----------------
__device__ __nv_bfloat16 g_xh[(size_t)M_ * D_];
__device__ __nv_bfloat16 g_xl[(size_t)M_ * D_];
__device__ __nv_bfloat16 g_Wh[(size_t)NP * D_];
__device__ __nv_bfloat16 g_Wl[(size_t)NP * D_];
__device__ float         g_P [(size_t)M_ * NP];
__device__ float         g_qkv[(size_t)M_ * 6144];
__device__ float         g_decay[(size_t)M_ * 2048];
__device__ float         g_vT[(size_t)64 * 128 * 2048];   // [bh][j][t]
__device__ float         g_betaT[(size_t)64 * 2048];      // [bh][t]
__device__ float         g_oscan[(size_t)M_ * 2048];
__device__ __nv_bfloat16 g_yh[(size_t)M_ * 2048];
__device__ __nv_bfloat16 g_yl[(size_t)M_ * 2048];
__device__ __nv_bfloat16 g_W2h[(size_t)D_ * 2048];
__device__ __nv_bfloat16 g_W2l[(size_t)D_ * 2048];

// ---------------- small helpers ----------------
__device__ __forceinline__ float sigf(float z) { return 1.f / (1.f + __expf(-z)); }

__device__ __forceinline__ void ldm4(uint32_t* r, uint32_t addr) {
    asm volatile("ldmatrix.sync.aligned.m8n8.x4.shared.b16 {%0,%1,%2,%3}, [%4];"
                 : "=r"(r[0]), "=r"(r[1]), "=r"(r[2]), "=r"(r[3]) : "r"(addr));
}
__device__ __forceinline__ void mma16816(float* c, const uint32_t* a, const uint32_t* b) {
    asm volatile("mma.sync.aligned.m16n8k16.row.col.f32.bf16.bf16.f32 "
                 "{%0,%1,%2,%3},{%4,%5,%6,%7},{%8,%9},{%0,%1,%2,%3};"
                 : "+f"(c[0]), "+f"(c[1]), "+f"(c[2]), "+f"(c[3])
                 : "r"(a[0]), "r"(a[1]), "r"(a[2]), "r"(a[3]), "r"(b[0]), "r"(b[1]));
}
__device__ __forceinline__ void cpa16(uint32_t saddr, const void* gaddr) {
    asm volatile("cp.async.cg.shared.global [%0], [%1], 16;" :: "r"(saddr), "l"(gaddr));
}
__device__ __forceinline__ void cpcommit() { asm volatile("cp.async.commit_group;"); }
template <int N> __device__ __forceinline__ void cpwait() {
    asm volatile("cp.async.wait_group %0;" :: "n"(N));
}

// ---- packed f32x2 ----
__device__ __forceinline__ unsigned long long f2pack(float lo, float hi) {
    unsigned long long r;
    asm("mov.b64 %0, {%1, %2};" : "=l"(r) : "f"(lo), "f"(hi));
    return r;
}
__device__ __forceinline__ unsigned long long f2fma(unsigned long long a, unsigned long long b, unsigned long long c) {
    unsigned long long r;
    asm("fma.rn.f32x2 %0, %1, %2, %3;" : "=l"(r) : "l"(a), "l"(b), "l"(c));
    return r;
}
__device__ __forceinline__ unsigned long long f2mul(unsigned long long a, unsigned long long b) {
    unsigned long long r;
    asm("mul.rn.f32x2 %0, %1, %2;" : "=l"(r) : "l"(a), "l"(b));
    return r;
}
__device__ __forceinline__ unsigned long long f2add(unsigned long long a, unsigned long long b) {
    unsigned long long r;
    asm("add.rn.f32x2 %0, %1, %2;" : "=l"(r) : "l"(a), "l"(b));
    return r;
}
__device__ __forceinline__ float f2lo(unsigned long long x) { return __uint_as_float((uint32_t)x); }
__device__ __forceinline__ float f2hi(unsigned long long x) { return __uint_as_float((uint32_t)(x >> 32)); }

// ---------------- split fp32 -> (hi, lo) bf16, float4-vectorized ----------------
__global__ void split_f32_v4(const float* __restrict__ src, __nv_bfloat16* __restrict__ hi,
                             __nv_bfloat16* __restrict__ lo, size_t n4) {
    size_t i = (size_t)blockIdx.x * blockDim.x + threadIdx.x;
    if (i >= n4) return;
    float4 v = ((const float4*)src)[i];
    __nv_bfloat16 hx = __float2bfloat16(v.x), hy = __float2bfloat16(v.y);
    __nv_bfloat16 hz = __float2bfloat16(v.z), hw = __float2bfloat16(v.w);
    __nv_bfloat162* hp = (__nv_bfloat162*)hi;
    __nv_bfloat162* lp = (__nv_bfloat162*)lo;
    hp[i * 2]     = __nv_bfloat162(hx, hy);
    hp[i * 2 + 1] = __nv_bfloat162(hz, hw);
    lp[i * 2]     = __nv_bfloat162(__float2bfloat16(v.x - __bfloat162float(hx)),
                                   __float2bfloat16(v.y - __bfloat162float(hy)));
    lp[i * 2 + 1] = __nv_bfloat162(__float2bfloat16(v.z - __bfloat162float(hz)),
                                   __float2bfloat16(v.w - __bfloat162float(hw)));
}

// ---------------- build fused+padded weight matrix, layout q|k|v|a|b|g ----------------
__global__ void build_wcat(const float* __restrict__ Wq, const float* __restrict__ Wk,
                           const float* __restrict__ Wv, const float* __restrict__ Wa,
                           const float* __restrict__ Wg, const float* __restrict__ Wb) {
    size_t i = (size_t)blockIdx.x * blockDim.x + threadIdx.x;   // over float4s
    if (i >= (size_t)NP * D_ / 4) return;
    int n = (int)(i / (D_ / 4));
    int d4 = (int)(i % (D_ / 4));
    float4 v = make_float4(0.f, 0.f, 0.f, 0.f);
    if      (n < 2048)  v = ((const float4*)Wq)[(size_t)n * (D_ / 4) + d4];
    else if (n < 4096)  v = ((const float4*)Wk)[(size_t)(n - 2048) * (D_ / 4) + d4];
    else if (n < 6144)  v = ((const float4*)Wv)[(size_t)(n - 4096) * (D_ / 4) + d4];
    else if (n < 8192)  v = ((const float4*)Wa)[(size_t)(n - 6144) * (D_ / 4) + d4];
    else if (n < 8208)  v = ((const float4*)Wb)[(size_t)(n - 8192) * (D_ / 4) + d4];
    else if (n >= 8320) v = ((const float4*)Wg)[(size_t)(n - 8320) * (D_ / 4) + d4];
    __nv_bfloat16 hx = __float2bfloat16(v.x), hy = __float2bfloat16(v.y);
    __nv_bfloat16 hz = __float2bfloat16(v.z), hw = __float2bfloat16(v.w);
    __nv_bfloat162* hp = (__nv_bfloat162*)g_Wh;
    __nv_bfloat162* lp = (__nv_bfloat162*)g_Wl;
    hp[i * 2]     = __nv_bfloat162(hx, hy);
    hp[i * 2 + 1] = __nv_bfloat162(hz, hw);
    lp[i * 2]     = __nv_bfloat162(__float2bfloat16(v.x - __bfloat162float(hx)),
                                   __float2bfloat16(v.y - __bfloat162float(hy)));
    lp[i * 2 + 1] = __nv_bfloat162(__float2bfloat16(v.z - __bfloat162float(hz)),
                                   __float2bfloat16(v.w - __bfloat162float(hw)));
}

// ---------------- split-bf16 GEMM (measured-best config) + N-tile offset ----------------
__device__ __forceinline__ void gemm_issue_stage(
    uint32_t smem, int stage, int tid,
    const __nv_bfloat16* Ah, const __nv_bfloat16* Al,
    const __nv_bfloat16* Bh, const __nv_bfloat16* Bl,
    int m0, int n0, int k0, int Kd)
{
#pragma unroll
    for (int i = 0; i < 2; i++) {
        int idx = tid + i * 256;
        int row = idx >> 2, ch = idx & 3;
        int pch = ch ^ ((row >> 1) & 3);
        uint32_t so = smem + stage * 32768 + row * 64 + pch * 16;
        size_t ga = (size_t)(m0 + row) * Kd + k0 + ch * 8;
        size_t gb = (size_t)(n0 + row) * Kd + k0 + ch * 8;
        cpa16(so,         Ah + ga);
        cpa16(so + 8192,  Al + ga);
        cpa16(so + 16384, Bh + gb);
        cpa16(so + 24576, Bl + gb);
    }
}

__global__ void __launch_bounds__(256, 2) gemm_split(
    const __nv_bfloat16* __restrict__ Ah, const __nv_bfloat16* __restrict__ Al,
    const __nv_bfloat16* __restrict__ Bh, const __nv_bfloat16* __restrict__ Bl,
    float* __restrict__ C, int M, int N, int Kd, int ntile0)
{
    extern __shared__ char sm_[];
    uint32_t smem = (uint32_t)__cvta_generic_to_shared(sm_);
    int tid = threadIdx.x;
    int warp = tid >> 5, lane = tid & 31;
    int wm = warp >> 2, wn = warp & 3;
    int m0 = blockIdx.y * 128, n0 = (blockIdx.x + ntile0) * 128;

    float acc[4][4][4];
#pragma unroll
    for (int a = 0; a < 4; a++)
#pragma unroll
        for (int b = 0; b < 4; b++)
#pragma unroll
            for (int c = 0; c < 4; c++) acc[a][b][c] = 0.f;

    int nkt = Kd >> 5;
    gemm_issue_stage(smem, 0, tid, Ah, Al, Bh, Bl, m0, n0, 0, Kd);
    cpcommit();

    for (int kt = 0; kt < nkt; kt++) {
        if (kt + 1 < nkt) {
            gemm_issue_stage(smem, (kt + 1) & 1, tid, Ah, Al, Bh, Bl, m0, n0, (kt + 1) * 32, Kd);
            cpcommit();
            cpwait<1>();
        } else {
            cpwait<0>();
        }
        __syncthreads();

        uint32_t base = smem + (kt & 1) * 32768;
#pragma unroll
        for (int k16 = 0; k16 < 2; k16++) {
            uint32_t a_h[4][4], a_l[4][4];
#pragma unroll
            for (int ms = 0; ms < 4; ms++) {
                int r = wm * 64 + ms * 16 + (lane & 15);
                int ch = k16 * 2 + (lane >> 4);
                int pch = ch ^ ((r >> 1) & 3);
                uint32_t ad = base + r * 64 + pch * 16;
                ldm4(a_h[ms], ad);
                ldm4(a_l[ms], ad + 8192);
            }
            uint32_t b_h[2][4], b_l[2][4];
#pragma unroll
            for (int ns = 0; ns < 2; ns++) {
                int r = wn * 32 + ns * 16 + (lane & 7) + ((lane >> 4) << 3);
                int ch = k16 * 2 + ((lane >> 3) & 1);
                int pch = ch ^ ((r >> 1) & 3);
                uint32_t ad = base + 16384 + r * 64 + pch * 16;
                ldm4(b_h[ns], ad);
                ldm4(b_l[ns], ad + 8192);
            }
#pragma unroll
            for (int ms = 0; ms < 4; ms++)
#pragma unroll
                for (int j = 0; j < 4; j++) {
                    const uint32_t* bhp = &b_h[j >> 1][(j & 1) * 2];
                    const uint32_t* blp = &b_l[j >> 1][(j & 1) * 2];
                    mma16816(acc[ms][j], a_h[ms], bhp);   // hi*hi
                    mma16816(acc[ms][j], a_h[ms], blp);   // hi*lo
                    mma16816(acc[ms][j], a_l[ms], bhp);   // lo*hi
                }
        }
        __syncthreads();
    }

#pragma unroll
    for (int ms = 0; ms < 4; ms++)
#pragma unroll
        for (int j = 0; j < 4; j++) {
            int row = m0 + wm * 64 + ms * 16 + (lane >> 2);
            int col = n0 + wn * 32 + j * 8 + (lane & 3) * 2;
            float2 v0; v0.x = acc[ms][j][0]; v0.y = acc[ms][j][1];
            float2 v1; v1.x = acc[ms][j][2]; v1.y = acc[ms][j][3];
            *(float2*)(C + (size_t)row * N + col)       = v0;
            *(float2*)(C + (size_t)(row + 8) * N + col) = v1;
        }
}

// ---------------- depthwise causal conv (K=4) + SiLU, 4 channels/thread ----------------
__global__ void conv_silu_v4(const float* __restrict__ cqw, const float* __restrict__ cqb,
                             const float* __restrict__ ckw, const float* __restrict__ ckb,
                             const float* __restrict__ cvw, const float* __restrict__ cvb) {
    size_t i = (size_t)blockIdx.x * blockDim.x + threadIdx.x;
    if (i >= (size_t)M_ * 1536) return;
    int c4 = (int)(i % 1536);
    size_t r = i / 1536;
    int t = (int)(r & (T_ - 1));
    int c = c4 * 4;

    const float* w;
    const float* bias;
    if (c < 2048)      { w = cqw + (size_t)c * 4;          bias = cqb + c; }
    else if (c < 4096) { w = ckw + (size_t)(c - 2048) * 4; bias = ckb + (c - 2048); }
    else               { w = cvw + (size_t)(c - 4096) * 4; bias = cvb + (c - 4096); }

    const float* src = g_P + r * (size_t)NP + c;
    float4 t0 = (t >= 3) ? *(const float4*)(src - 3 * NP) : make_float4(0.f, 0.f, 0.f, 0.f);
    float4 t1 = (t >= 2) ? *(const float4*)(src - 2 * NP) : make_float4(0.f, 0.f, 0.f, 0.f);
    float4 t2 = (t >= 1) ? *(const float4*)(src - 1 * NP) : make_float4(0.f, 0.f, 0.f, 0.f);
    float4 t3 = *(const float4*)(src);

    float4 w0 = *(const float4*)(w);
    float4 w1 = *(const float4*)(w + 4);
    float4 w2 = *(const float4*)(w + 8);
    float4 w3 = *(const float4*)(w + 12);
    float4 bi = *(const float4*)(bias);

    float4 out;
    {
        float a = bi.x + w0.x * t0.x + w0.y * t1.x + w0.z * t2.x + w0.w * t3.x;
        out.x = a * sigf(a);
        float b = bi.y + w1.x * t0.y + w1.y * t1.y + w1.z * t2.y + w1.w * t3.y;
        out.y = b * sigf(b);
        float cc = bi.z + w2.x * t0.z + w2.y * t1.z + w2.z * t2.z + w2.w * t3.z;
        out.z = cc * sigf(cc);
        float d = bi.w + w3.x * t0.w + w3.y * t1.w + w3.z * t2.w + w3.w * t3.w;
        out.w = d * sigf(d);
    }
    *(float4*)(g_qkv + r * 6144 + c) = out;
}

// ---------------- tiled transpose of v ----------------
__global__ void transpose_v() {
    __shared__ float tile[32][33];
    int bh = blockIdx.x;
    int b = bh >> 4, h = bh & 15;
    int j0 = blockIdx.y * 32;
    int t0 = blockIdx.z * 32;
    int tx = threadIdx.x, ty = threadIdx.y;   // 32 x 8

    const float* src = g_qkv + ((size_t)b * T_ + t0) * 6144 + CV + h * 128 + j0;
#pragma unroll
    for (int p = 0; p < 4; p++) {
        int tt = ty + p * 8;
        tile[tt][tx] = src[(size_t)tt * 6144 + tx];
    }
    __syncthreads();
    float* dst = g_vT + (((size_t)bh) * 128 + j0) * 2048 + t0;
#pragma unroll
    for (int p = 0; p < 4; p++) {
        int jj = ty + p * 8;
        dst[(size_t)jj * 2048 + tx] = tile[tx][jj];
    }
}

// ---------------- decay (float4) + beta fused ----------------
__global__ void decay_beta_v4(const float* __restrict__ ba, const float* __restrict__ bb) {
    size_t i = (size_t)blockIdx.x * blockDim.x + threadIdx.x;
    if (i >= (size_t)M_ * 512) return;
    int c4 = (int)(i % 512);
    size_t r = i / 512;
    int c = c4 * 4;
    float4 p = *(const float4*)(g_P + r * (size_t)NP + CA + c);
    float4 bv = *(const float4*)(ba + c);
    float4 o;
    o.x = fmaxf(sigf(p.x + bv.x), 1e-6f);
    o.y = fmaxf(sigf(p.y + bv.y), 1e-6f);
    o.z = fmaxf(sigf(p.z + bv.z), 1e-6f);
    o.w = fmaxf(sigf(p.w + bv.w), 1e-6f);
    *(float4*)(g_decay + r * 2048 + c) = o;
    if (c4 < 4) {            // threads covering c=0..15 also produce beta for h=c..c+3
        int b = (int)(r >> 11), t = (int)(r & (T_ - 1));
#pragma unroll
        for (int e = 0; e < 4; e++) {
            int h = c + e;
            g_betaT[((size_t)(b * 16 + h)) * 2048 + t] =
                sigf(g_P[r * (size_t)NP + CB + h] + bb[h]);
        }
    }
}

// ---------------- gated delta-rule scan: pointer-increment, zero per-iter addr math ----------------
__device__ __forceinline__ unsigned long long red32p(unsigned long long x) {
    x = f2add(x, __shfl_xor_sync(0xffffffffu, x, 1));
    x = f2add(x, __shfl_xor_sync(0xffffffffu, x, 2));
    x = f2add(x, __shfl_xor_sync(0xffffffffu, x, 4));
    x = f2add(x, __shfl_xor_sync(0xffffffffu, x, 8));
    x = f2add(x, __shfl_xor_sync(0xffffffffu, x, 16));
    return x;
}
__device__ __forceinline__ float f4c(const float4& v, int u) {
    return u == 0 ? v.x : (u == 1 ? v.y : (u == 2 ? v.z : v.w));
}

// one delta-rule step; PF=1 prefetches group-base+const-offset, PF=0 reuses regs
template <int U, int PF>
__device__ __forceinline__ void scan_step(
    unsigned long long& sp0, unsigned long long& sp1,
    unsigned long long& sp2, unsigned long long& sp3,
    float4& k4, float4& d4, float4& q4,
    const float4 vA, const float4 vB, const float4 bt4,
    const float* kb, const float* qb, const float* db, float* ob, int lane,
    float scale)
{
    unsigned long long kp0 = f2pack(k4.x, k4.x), kp1 = f2pack(k4.y, k4.y);
    unsigned long long kp2 = f2pack(k4.z, k4.z), kp3 = f2pack(k4.w, k4.w);
    unsigned long long dp0 = f2pack(d4.x, d4.x), dp1 = f2pack(d4.y, d4.y);
    unsigned long long dp2 = f2pack(d4.z, d4.z), dp3 = f2pack(d4.w, d4.w);

    sp0 = f2mul(sp0, dp0); sp1 = f2mul(sp1, dp1);
    sp2 = f2mul(sp2, dp2); sp3 = f2mul(sp3, dp3);
    float4 nd;
    if (PF) nd = *(const float4*)(db + (U + 1) * 2048);

    unsigned long long acc = f2mul(kp0, sp0);
    acc = f2fma(kp1, sp1, acc);
    acc = f2fma(kp2, sp2, acc);
    acc = f2fma(kp3, sp3, acc);
    acc = red32p(acc);
    float p0 = f2lo(acc), p1 = f2hi(acc);

    float btc = f4c(bt4, U);
    float be0 = btc * (f4c(vA, U) - p0);
    float be1 = btc * (f4c(vB, U) - p1);
    unsigned long long bep = f2pack(be0, be1);

    sp0 = f2fma(bep, kp0, sp0); sp1 = f2fma(bep, kp1, sp1);
    sp2 = f2fma(bep, kp2, sp2); sp3 = f2fma(bep, kp3, sp3);
    float4 nk;
    if (PF) nk = *(const float4*)(kb + (U + 1) * 6144);

    unsigned long long qp0 = f2pack(q4.x, q4.x), qp1 = f2pack(q4.y, q4.y);
    unsigned long long qp2 = f2pack(q4.z, q4.z), qp3 = f2pack(q4.w, q4.w);
    unsigned long long oacc = f2mul(qp0, sp0);
    oacc = f2fma(qp1, sp1, oacc);
    oacc = f2fma(qp2, sp2, oacc);
    oacc = f2fma(qp3, sp3, oacc);
    float4 nq;
    if (PF) nq = *(const float4*)(qb + (U + 1) * 6144);
    oacc = red32p(oacc);

    if (lane < 2) ob[U * 2048 + lane] = (lane ? f2hi(oacc) : f2lo(oacc)) * scale;

    if (PF) { k4 = nk; d4 = nd; q4 = nq; }
}

__global__ void __launch_bounds__(128, 7) kda_scan() {
    int warp = threadIdx.x >> 5, lane = threadIdx.x & 31;
    int bh = blockIdx.x;
    int b = bh >> 4, h = bh & 15;
    int wj = blockIdx.y * 4 + warp;
    int j0 = wj * 2;
    size_t rbase = (size_t)b * T_;

    const float* kb  = g_qkv   + rbase * 6144 + CK + h * 128 + lane * 4;
    const float* qb  = g_qkv   + rbase * 6144 + CQ + h * 128 + lane * 4;
    const float* db  = g_decay + rbase * 2048 + h * 128 + lane * 4;
    const float* v0p = g_vT + (((size_t)bh) * 128 + j0) * 2048;
    const float* v1p = v0p + 2048;
    const float* btp = g_betaT + (size_t)bh * 2048;
    float* ob = g_oscan + rbase * 2048 + h * 128 + j0;

    unsigned long long sp0 = 0ull, sp1 = 0ull, sp2 = 0ull, sp3 = 0ull;
    const float scale = 0.08838834764831845f;

    float4 k4 = *(const float4*)(kb);
    float4 d4 = *(const float4*)(db);
    float4 q4 = *(const float4*)(qb);

    // main groups: prefetch uses group-base + compile-time offsets only
    for (int tg = 0; tg < T_ - 4; tg += 4) {
        float4 vA  = *(const float4*)(v0p);
        float4 vB  = *(const float4*)(v1p);
        float4 bt4 = *(const float4*)(btp);
        scan_step<0, 1>(sp0, sp1, sp2, sp3, k4, d4, q4, vA, vB, bt4, kb, qb, db, ob, lane, scale);
        scan_step<1, 1>(sp0, sp1, sp2, sp3, k4, d4, q4, vA, vB, bt4, kb, qb, db, ob, lane, scale);
        scan_step<2, 1>(sp0, sp1, sp2, sp3, k4, d4, q4, vA, vB, bt4, kb, qb, db, ob, lane, scale);
        scan_step<3, 1>(sp0, sp1, sp2, sp3, k4, d4, q4, vA, vB, bt4, kb, qb, db, ob, lane, scale);
        kb += 4 * 6144; qb += 4 * 6144; db += 4 * 2048; ob += 4 * 2048;
        v0p += 4; v1p += 4; btp += 4;
    }
    // last group (tg = T_-4): prefetch only within bounds
    {
        float4 vA  = *(const float4*)(v0p);
        float4 vB  = *(const float4*)(v1p);
        float4 bt4 = *(const float4*)(btp);
        scan_step<0, 1>(sp0, sp1, sp2, sp3, k4, d4, q4, vA, vB, bt4, kb, qb, db, ob, lane, scale);
        scan_step<1, 1>(sp0, sp1, sp2, sp3, k4, d4, q4, vA, vB, bt4, kb, qb, db, ob, lane, scale);
        scan_step<2, 1>(sp0, sp1, sp2, sp3, k4, d4, q4, vA, vB, bt4, kb, qb, db, ob, lane, scale);
        scan_step<3, 0>(sp0, sp1, sp2, sp3, k4, d4, q4, vA, vB, bt4, kb, qb, db, ob, lane, scale);
    }
}

// ---------------- per-head LayerNorm + sigmoid gate + split to bf16 hi/lo ----------------
__global__ void ln_gate(const float* __restrict__ ln_w, const float* __restrict__ ln_b) {
    int gwarp = (int)(((size_t)blockIdx.x * blockDim.x + threadIdx.x) >> 5);
    int lane = threadIdx.x & 31;
    if (gwarp >= M_ * H_) return;
    int h = gwarp & 15;
    size_t r = (size_t)(gwarp >> 4);

    const float* obp = g_oscan + r * 2048 + h * 128;
    float4 o4 = *(const float4*)(obp + lane * 4);
    float sum = o4.x + o4.y + o4.z + o4.w;
#pragma unroll
    for (int off = 16; off; off >>= 1) sum += __shfl_xor_sync(0xffffffffu, sum, off);
    float mu = sum * (1.f / 128.f);
    float dx = o4.x - mu, dy = o4.y - mu, dz = o4.z - mu, dw = o4.w - mu;
    float sq = dx * dx + dy * dy + dz * dz + dw * dw;
#pragma unroll
    for (int off = 16; off; off >>= 1) sq += __shfl_xor_sync(0xffffffffu, sq, off);
    float rs = rsqrtf(sq * (1.f / 128.f) + 1e-5f);

    float vals[4] = {dx, dy, dz, dw};
#pragma unroll
    for (int e = 0; e < 4; e++) {
        int jj = lane * 4 + e;
        float y = vals[e] * rs * ln_w[jj] + ln_b[jj];
        float gate = sigf(g_P[r * (size_t)NP + CG + h * 128 + jj]);
        y *= gate;
        size_t idx = r * 2048 + h * 128 + jj;
        __nv_bfloat16 hh = __float2bfloat16(y);
        g_yh[idx] = hh;
        g_yl[idx] = __float2bfloat16(y - __bfloat162float(hh));
    }
}

// ---------------- launch ----------------
extern "C" void kernel_launch(void* const* d_in, const int* in_sizes, int n_in,
                              void* d_out, int out_size) {
    const float* x    = (const float*)d_in[0];
    const float* Wq   = (const float*)d_in[1];
    const float* Wk   = (const float*)d_in[2];
    const float* Wv   = (const float*)d_in[3];
    const float* Wa   = (const float*)d_in[4];
    const float* ba   = (const float*)d_in[5];
    const float* Wb   = (const float*)d_in[6];
    const float* bb   = (const float*)d_in[7];
    const float* Wg   = (const float*)d_in[8];
    const float* Wo   = (const float*)d_in[9];
    const float* cqw  = (const float*)d_in[10];
    const float* cqb  = (const float*)d_in[11];
    const float* ckw  = (const float*)d_in[12];
    const float* ckb  = (const float*)d_in[13];
    const float* cvw  = (const float*)d_in[14];
    const float* cvb  = (const float*)d_in[15];
    const float* ln_w = (const float*)d_in[16];
    const float* ln_b = (const float*)d_in[17];
    float* out = (float*)d_out;

    static __nv_bfloat16 *pxh = nullptr, *pxl, *pWh, *pWl, *pyh, *pyl, *pW2h, *pW2l;
    static float *pP;
    static cudaStream_t s1;
    static cudaEvent_t ev0, ev_fork, ev_join;
    if (!pxh) {
        cudaGetSymbolAddress((void**)&pxh, g_xh);
        cudaGetSymbolAddress((void**)&pxl, g_xl);
        cudaGetSymbolAddress((void**)&pWh, g_Wh);
        cudaGetSymbolAddress((void**)&pWl, g_Wl);
        cudaGetSymbolAddress((void**)&pP,  g_P);
        cudaGetSymbolAddress((void**)&pyh, g_yh);
        cudaGetSymbolAddress((void**)&pyl, g_yl);
        cudaGetSymbolAddress((void**)&pW2h, g_W2h);
        cudaGetSymbolAddress((void**)&pW2l, g_W2l);
        cudaFuncSetAttribute(gemm_split, cudaFuncAttributeMaxDynamicSharedMemorySize, 65536);
        cudaStreamCreateWithFlags(&s1, cudaStreamNonBlocking);
        cudaEventCreateWithFlags(&ev0, cudaEventDisableTiming);
        cudaEventCreateWithFlags(&ev_fork, cudaEventDisableTiming);
        cudaEventCreateWithFlags(&ev_join, cudaEventDisableTiming);
    }

    const int TPB = 256;

    // fork side stream early: Wo split has no dependencies
    cudaEventRecord(ev0, 0);
    cudaStreamWaitEvent(s1, ev0, 0);
    split_f32_v4<<<(int)(((size_t)D_ * 2048 / 4 + TPB - 1) / TPB), TPB, 0, s1>>>(
        Wo, pW2h, pW2l, (size_t)D_ * 2048 / 4);

    // main: x split + fused weight build
    split_f32_v4<<<(int)(((size_t)M_ * D_ / 4 + TPB - 1) / TPB), TPB>>>(x, pxh, pxl, (size_t)M_ * D_ / 4);
    build_wcat<<<(int)(((size_t)NP * D_ / 4 + TPB - 1) / TPB), TPB>>>(Wq, Wk, Wv, Wa, Wg, Wb);
    cudaEventRecord(ev_fork, 0);

    // 2a) main: projection GEMM for q|k|v|a|b cols (65 tiles)
    gemm_split<<<dim3(65, M_ / 128), 256, 65536>>>(pxh, pxl, pWh, pWl, pP, M_, NP, D_, 0);
    // 2b) side: g-column GEMM (16 tiles), concurrent with 2a (round-14 best schedule)
    cudaStreamWaitEvent(s1, ev_fork, 0);
    gemm_split<<<dim3(16, M_ / 128), 256, 65536, s1>>>(pxh, pxl, pWh, pWl, pP, M_, NP, D_, 65);
    cudaEventRecord(ev_join, s1);

    // 3) conv + transpose + fused decay/beta (main stream)
    conv_silu_v4<<<(int)(((size_t)M_ * 1536 + TPB - 1) / TPB), TPB>>>(cqw, cqb, ckw, ckb, cvw, cvb);
    transpose_v<<<dim3(64, 4, 64), dim3(32, 8)>>>();
    decay_beta_v4<<<(int)(((size_t)M_ * 512 + TPB - 1) / TPB), TPB>>>(ba, bb);

    // 5) gated delta-rule scan
    kda_scan<<<dim3(B_ * H_, 16), 128>>>();

    // join: ln_gate needs the g columns from 2b
    cudaStreamWaitEvent(0, ev_join, 0);

    // 6) LayerNorm + gate + bf16 split
    ln_gate<<<M_ * H_ / 8, 256>>>(ln_w, ln_b);

    // 7) output projection: out = y @ Wo^T   (8192 x 2048 x 2048)
    gemm_split<<<dim3(16, M_ / 128), 256, 65536>>>(pyh, pyl, pW2h, pW2l, out, M_, 2048, D_, 0);
}

// round 17
// speedup vs baseline: 1.0187x; 1.0018x over previous
#include <cuda_runtime.h>
#include <cuda_bf16.h>
#include <cstdint>
#include <cstddef>

#define B_ 4
#define T_ 2048
#define D_ 2048
#define H_ 16
#define M_ 8192              // B*T
#define NP 10368             // fused projection cols: q|k|v|a|b(pad)|g
#define CQ 0
#define CK 2048
#define CV 4096
#define CA 6144
#define CB 8192              // 16 real cols, padded to 128
#define CG 8320              // 2048 cols, tail of the matrix

// ---------------- scratch (static device globals; no allocation) ----------------
__device__ __nv_bfloat16 g_xh[(size_t)M_ * D_];
__device__ __nv_bfloat16 g_xl[(size_t)M_ * D_];
__device__ __nv_bfloat16 g_Wh[(size_t)NP * D_];
__device__ __nv_bfloat16 g_Wl[(size_t)NP * D_];
__device__ float         g_P [(size_t)M_ * NP];
__device__ float         g_qkv[(size_t)M_ * 6144];
__device__ float         g_decay[(size_t)M_ * 2048];
__device__ float         g_vT[(size_t)64 * 128 * 2048];   // [bh][j][t]
__device__ float         g_betaT[(size_t)64 * 2048];      // [bh][t]
__device__ float         g_oscan[(size_t)M_ * 2048];
__device__ __nv_bfloat16 g_yh[(size_t)M_ * 2048];
__device__ __nv_bfloat16 g_yl[(size_t)M_ * 2048];
__device__ __nv_bfloat16 g_W2h[(size_t)D_ * 2048];
__device__ __nv_bfloat16 g_W2l[(size_t)D_ * 2048];

// ---------------- small helpers ----------------
__device__ __forceinline__ float sigf(float z) { return 1.f / (1.f + __expf(-z)); }

__device__ __forceinline__ void ldm4(uint32_t* r, uint32_t addr) {
    asm volatile("ldmatrix.sync.aligned.m8n8.x4.shared.b16 {%0,%1,%2,%3}, [%4];"
                 : "=r"(r[0]), "=r"(r[1]), "=r"(r[2]), "=r"(r[3]) : "r"(addr));
}
__device__ __forceinline__ void mma16816(float* c, const uint32_t* a, const uint32_t* b) {
    asm volatile("mma.sync.aligned.m16n8k16.row.col.f32.bf16.bf16.f32 "
                 "{%0,%1,%2,%3},{%4,%5,%6,%7},{%8,%9},{%0,%1,%2,%3};"
                 : "+f"(c[0]), "+f"(c[1]), "+f"(c[2]), "+f"(c[3])
                 : "r"(a[0]), "r"(a[1]), "r"(a[2]), "r"(a[3]), "r"(b[0]), "r"(b[1]));
}
__device__ __forceinline__ void cpa16(uint32_t saddr, const void* gaddr) {
    asm volatile("cp.async.cg.shared.global [%0], [%1], 16;" :: "r"(saddr), "l"(gaddr));
}
__device__ __forceinline__ void cpcommit() { asm volatile("cp.async.commit_group;"); }
template <int N> __device__ __forceinline__ void cpwait() {
    asm volatile("cp.async.wait_group %0;" :: "n"(N));
}

// ---- packed f32x2 ----
__device__ __forceinline__ unsigned long long f2pack(float lo, float hi) {
    unsigned long long r;
    asm("mov.b64 %0, {%1, %2};" : "=l"(r) : "f"(lo), "f"(hi));
    return r;
}
__device__ __forceinline__ unsigned long long f2fma(unsigned long long a, unsigned long long b, unsigned long long c) {
    unsigned long long r;
    asm("fma.rn.f32x2 %0, %1, %2, %3;" : "=l"(r) : "l"(a), "l"(b), "l"(c));
    return r;
}
__device__ __forceinline__ unsigned long long f2mul(unsigned long long a, unsigned long long b) {
    unsigned long long r;
    asm("mul.rn.f32x2 %0, %1, %2;" : "=l"(r) : "l"(a), "l"(b));
    return r;
}
__device__ __forceinline__ unsigned long long f2add(unsigned long long a, unsigned long long b) {
    unsigned long long r;
    asm("add.rn.f32x2 %0, %1, %2;" : "=l"(r) : "l"(a), "l"(b));
    return r;
}
__device__ __forceinline__ float f2lo(unsigned long long x) { return __uint_as_float((uint32_t)x); }
__device__ __forceinline__ float f2hi(unsigned long long x) { return __uint_as_float((uint32_t)(x >> 32)); }

// ---------------- split fp32 -> (hi, lo) bf16, float4-vectorized ----------------
__global__ void split_f32_v4(const float* __restrict__ src, __nv_bfloat16* __restrict__ hi,
                             __nv_bfloat16* __restrict__ lo, size_t n4) {
    size_t i = (size_t)blockIdx.x * blockDim.x + threadIdx.x;
    if (i >= n4) return;
    float4 v = ((const float4*)src)[i];
    __nv_bfloat16 hx = __float2bfloat16(v.x), hy = __float2bfloat16(v.y);
    __nv_bfloat16 hz = __float2bfloat16(v.z), hw = __float2bfloat16(v.w);
    __nv_bfloat162* hp = (__nv_bfloat162*)hi;
    __nv_bfloat162* lp = (__nv_bfloat162*)lo;
    hp[i * 2]     = __nv_bfloat162(hx, hy);
    hp[i * 2 + 1] = __nv_bfloat162(hz, hw);
    lp[i * 2]     = __nv_bfloat162(__float2bfloat16(v.x - __bfloat162float(hx)),
                                   __float2bfloat16(v.y - __bfloat162float(hy)));
    lp[i * 2 + 1] = __nv_bfloat162(__float2bfloat16(v.z - __bfloat162float(hz)),
                                   __float2bfloat16(v.w - __bfloat162float(hw)));
}

// ---------------- build fused+padded weight matrix, layout q|k|v|a|b|g ----------------
__global__ void build_wcat(const float* __restrict__ Wq, const float* __restrict__ Wk,
                           const float* __restrict__ Wv, const float* __restrict__ Wa,
                           const float* __restrict__ Wg, const float* __restrict__ Wb) {
    size_t i = (size_t)blockIdx.x * blockDim.x + threadIdx.x;   // over float4s
    if (i >= (size_t)NP * D_ / 4) return;
    int n = (int)(i / (D_ / 4));
    int d4 = (int)(i % (D_ / 4));
    float4 v = make_float4(0.f, 0.f, 0.f, 0.f);
    if      (n < 2048)  v = ((const float4*)Wq)[(size_t)n * (D_ / 4) + d4];
    else if (n < 4096)  v = ((const float4*)Wk)[(size_t)(n - 2048) * (D_ / 4) + d4];
    else if (n < 6144)  v = ((const float4*)Wv)[(size_t)(n - 4096) * (D_ / 4) + d4];
    else if (n < 8192)  v = ((const float4*)Wa)[(size_t)(n - 6144) * (D_ / 4) + d4];
    else if (n < 8208)  v = ((const float4*)Wb)[(size_t)(n - 8192) * (D_ / 4) + d4];
    else if (n >= 8320) v = ((const float4*)Wg)[(size_t)(n - 8320) * (D_ / 4) + d4];
    __nv_bfloat16 hx = __float2bfloat16(v.x), hy = __float2bfloat16(v.y);
    __nv_bfloat16 hz = __float2bfloat16(v.z), hw = __float2bfloat16(v.w);
    __nv_bfloat162* hp = (__nv_bfloat162*)g_Wh;
    __nv_bfloat162* lp = (__nv_bfloat162*)g_Wl;
    hp[i * 2]     = __nv_bfloat162(hx, hy);
    hp[i * 2 + 1] = __nv_bfloat162(hz, hw);
    lp[i * 2]     = __nv_bfloat162(__float2bfloat16(v.x - __bfloat162float(hx)),
                                   __float2bfloat16(v.y - __bfloat162float(hy)));
    lp[i * 2 + 1] = __nv_bfloat162(__float2bfloat16(v.z - __bfloat162float(hz)),
                                   __float2bfloat16(v.w - __bfloat162float(hw)));
}

// ---------------- split-bf16 GEMM: 3-stage pipeline, ONE barrier per K-tile ----------------
// Fill for stage kt+2 is issued AFTER compute(kt); it overwrites the stage computed
// at iter kt-1, which the barrier at the TOP of iter kt already ordered. smem 96KB/CTA.
__device__ __forceinline__ void gemm_issue_stage(
    uint32_t smem, int stage, int tid,
    const __nv_bfloat16* Ah, const __nv_bfloat16* Al,
    const __nv_bfloat16* Bh, const __nv_bfloat16* Bl,
    int m0, int n0, int k0, int Kd)
{
#pragma unroll
    for (int i = 0; i < 2; i++) {
        int idx = tid + i * 256;
        int row = idx >> 2, ch = idx & 3;
        int pch = ch ^ ((row >> 1) & 3);
        uint32_t so = smem + stage * 32768 + row * 64 + pch * 16;
        size_t ga = (size_t)(m0 + row) * Kd + k0 + ch * 8;
        size_t gb = (size_t)(n0 + row) * Kd + k0 + ch * 8;
        cpa16(so,         Ah + ga);
        cpa16(so + 8192,  Al + ga);
        cpa16(so + 16384, Bh + gb);
        cpa16(so + 24576, Bl + gb);
    }
}

__global__ void __launch_bounds__(256, 2) gemm_split(
    const __nv_bfloat16* __restrict__ Ah, const __nv_bfloat16* __restrict__ Al,
    const __nv_bfloat16* __restrict__ Bh, const __nv_bfloat16* __restrict__ Bl,
    float* __restrict__ C, int M, int N, int Kd, int ntile0)
{
    extern __shared__ char sm_[];
    uint32_t smem = (uint32_t)__cvta_generic_to_shared(sm_);
    int tid = threadIdx.x;
    int warp = tid >> 5, lane = tid & 31;
    int wm = warp >> 2, wn = warp & 3;
    int m0 = blockIdx.y * 128, n0 = (blockIdx.x + ntile0) * 128;

    float acc[4][4][4];
#pragma unroll
    for (int a = 0; a < 4; a++)
#pragma unroll
        for (int b = 0; b < 4; b++)
#pragma unroll
            for (int c = 0; c < 4; c++) acc[a][b][c] = 0.f;

    int nkt = Kd >> 5;
    gemm_issue_stage(smem, 0, tid, Ah, Al, Bh, Bl, m0, n0, 0, Kd);
    cpcommit();
    gemm_issue_stage(smem, 1, tid, Ah, Al, Bh, Bl, m0, n0, 32, Kd);
    cpcommit();

    int scur = 0, snext = 2;
    for (int kt = 0; kt < nkt; kt++) {
        if (kt == nkt - 1) { cpwait<0>(); } else { cpwait<1>(); }
        __syncthreads();

        uint32_t base = smem + scur * 32768;
#pragma unroll
        for (int k16 = 0; k16 < 2; k16++) {
            uint32_t a_h[4][4], a_l[4][4];
#pragma unroll
            for (int ms = 0; ms < 4; ms++) {
                int r = wm * 64 + ms * 16 + (lane & 15);
                int ch = k16 * 2 + (lane >> 4);
                int pch = ch ^ ((r >> 1) & 3);
                uint32_t ad = base + r * 64 + pch * 16;
                ldm4(a_h[ms], ad);
                ldm4(a_l[ms], ad + 8192);
            }
            uint32_t b_h[2][4], b_l[2][4];
#pragma unroll
            for (int ns = 0; ns < 2; ns++) {
                int r = wn * 32 + ns * 16 + (lane & 7) + ((lane >> 4) << 3);
                int ch = k16 * 2 + ((lane >> 3) & 1);
                int pch = ch ^ ((r >> 1) & 3);
                uint32_t ad = base + 16384 + r * 64 + pch * 16;
                ldm4(b_h[ns], ad);
                ldm4(b_l[ns], ad + 8192);
            }
#pragma unroll
            for (int ms = 0; ms < 4; ms++)
#pragma unroll
                for (int j = 0; j < 4; j++) {
                    const uint32_t* bhp = &b_h[j >> 1][(j & 1) * 2];
                    const uint32_t* blp = &b_l[j >> 1][(j & 1) * 2];
                    mma16816(acc[ms][j], a_h[ms], bhp);   // hi*hi
                    mma16816(acc[ms][j], a_h[ms], blp);   // hi*lo
                    mma16816(acc[ms][j], a_l[ms], bhp);   // lo*hi
                }
        }

        if (kt + 2 < nkt) {
            gemm_issue_stage(smem, snext, tid, Ah, Al, Bh, Bl, m0, n0, (kt + 2) * 32, Kd);
            cpcommit();
        }
        scur++; if (scur == 3) scur = 0;
        snext++; if (snext == 3) snext = 0;
    }

#pragma unroll
    for (int ms = 0; ms < 4; ms++)
#pragma unroll
        for (int j = 0; j < 4; j++) {
            int row = m0 + wm * 64 + ms * 16 + (lane >> 2);
            int col = n0 + wn * 32 + j * 8 + (lane & 3) * 2;
            float2 v0; v0.x = acc[ms][j][0]; v0.y = acc[ms][j][1];
            float2 v1; v1.x = acc[ms][j][2]; v1.y = acc[ms][j][3];
            *(float2*)(C + (size_t)row * N + col)       = v0;
            *(float2*)(C + (size_t)(row + 8) * N + col) = v1;
        }
}

// ---------------- conv+SiLU / decay / beta, one kernel ----------------
__global__ void conv_decay_beta(const float* __restrict__ cqw, const float* __restrict__ cqb,
                                const float* __restrict__ ckw, const float* __restrict__ ckb,
                                const float* __restrict__ cvw, const float* __restrict__ cvb,
                                const float* __restrict__ ba, const float* __restrict__ bb) {
    size_t i = (size_t)blockIdx.x * blockDim.x + threadIdx.x;
    if (i >= (size_t)M_ * 2048) return;
    int c4 = (int)(i % 2048);
    size_t r = i / 2048;
    int t = (int)(r & (T_ - 1));

    if (c4 < 1536) {   // depthwise conv + SiLU over q|k|v
        int c = c4 * 4;
        const float* w;
        const float* bias;
        if (c < 2048)      { w = cqw + (size_t)c * 4;          bias = cqb + c; }
        else if (c < 4096) { w = ckw + (size_t)(c - 2048) * 4; bias = ckb + (c - 2048); }
        else               { w = cvw + (size_t)(c - 4096) * 4; bias = cvb + (c - 4096); }

        const float* src = g_P + r * (size_t)NP + c;
        float4 t0 = (t >= 3) ? *(const float4*)(src - 3 * NP) : make_float4(0.f, 0.f, 0.f, 0.f);
        float4 t1 = (t >= 2) ? *(const float4*)(src - 2 * NP) : make_float4(0.f, 0.f, 0.f, 0.f);
        float4 t2 = (t >= 1) ? *(const float4*)(src - 1 * NP) : make_float4(0.f, 0.f, 0.f, 0.f);
        float4 t3 = *(const float4*)(src);

        float4 w0 = *(const float4*)(w);
        float4 w1 = *(const float4*)(w + 4);
        float4 w2 = *(const float4*)(w + 8);
        float4 w3 = *(const float4*)(w + 12);
        float4 bi = *(const float4*)(bias);

        float4 out;
        float a = bi.x + w0.x * t0.x + w0.y * t1.x + w0.z * t2.x + w0.w * t3.x;
        out.x = a * sigf(a);
        float b = bi.y + w1.x * t0.y + w1.y * t1.y + w1.z * t2.y + w1.w * t3.y;
        out.y = b * sigf(b);
        float cc = bi.z + w2.x * t0.z + w2.y * t1.z + w2.z * t2.z + w2.w * t3.z;
        out.z = cc * sigf(cc);
        float d = bi.w + w3.x * t0.w + w3.y * t1.w + w3.z * t2.w + w3.w * t3.w;
        out.w = d * sigf(d);
        *(float4*)(g_qkv + r * 6144 + c) = out;
    } else {           // decay (+beta for first 4 groups)
        int c = (c4 - 1536) * 4;
        float4 p = *(const float4*)(g_P + r * (size_t)NP + CA + c);
        float4 bv = *(const float4*)(ba + c);
        float4 o;
        o.x = fmaxf(sigf(p.x + bv.x), 1e-6f);
        o.y = fmaxf(sigf(p.y + bv.y), 1e-6f);
        o.z = fmaxf(sigf(p.z + bv.z), 1e-6f);
        o.w = fmaxf(sigf(p.w + bv.w), 1e-6f);
        *(float4*)(g_decay + r * 2048 + c) = o;
        if (c < 16) {
            int b = (int)(r >> 11);
#pragma unroll
            for (int e = 0; e < 4; e++) {
                int h = c + e;
                g_betaT[((size_t)(b * 16 + h)) * 2048 + t] =
                    sigf(g_P[r * (size_t)NP + CB + h] + bb[h]);
            }
        }
    }
}

// ---------------- tiled transpose of v ----------------
__global__ void transpose_v() {
    __shared__ float tile[32][33];
    int bh = blockIdx.x;
    int b = bh >> 4, h = bh & 15;
    int j0 = blockIdx.y * 32;
    int t0 = blockIdx.z * 32;
    int tx = threadIdx.x, ty = threadIdx.y;   // 32 x 8

    const float* src = g_qkv + ((size_t)b * T_ + t0) * 6144 + CV + h * 128 + j0;
#pragma unroll
    for (int p = 0; p < 4; p++) {
        int tt = ty + p * 8;
        tile[tt][tx] = src[(size_t)tt * 6144 + tx];
    }
    __syncthreads();
    float* dst = g_vT + (((size_t)bh) * 128 + j0) * 2048 + t0;
#pragma unroll
    for (int p = 0; p < 4; p++) {
        int jj = ty + p * 8;
        dst[(size_t)jj * 2048 + tx] = tile[tx][jj];
    }
}

// ---------------- gated delta-rule scan (round-16 best) ----------------
__device__ __forceinline__ unsigned long long red32p(unsigned long long x) {
    x = f2add(x, __shfl_xor_sync(0xffffffffu, x, 1));
    x = f2add(x, __shfl_xor_sync(0xffffffffu, x, 2));
    x = f2add(x, __shfl_xor_sync(0xffffffffu, x, 4));
    x = f2add(x, __shfl_xor_sync(0xffffffffu, x, 8));
    x = f2add(x, __shfl_xor_sync(0xffffffffu, x, 16));
    return x;
}
__device__ __forceinline__ float f4c(const float4& v, int u) {
    return u == 0 ? v.x : (u == 1 ? v.y : (u == 2 ? v.z : v.w));
}

template <int U, int PF>
__device__ __forceinline__ void scan_step(
    unsigned long long& sp0, unsigned long long& sp1,
    unsigned long long& sp2, unsigned long long& sp3,
    float4& k4, float4& d4, float4& q4,
    const float4 vA, const float4 vB, const float4 bt4,
    const float* kb, const float* qb, const float* db, float* ob, int lane,
    float scale)
{
    unsigned long long kp0 = f2pack(k4.x, k4.x), kp1 = f2pack(k4.y, k4.y);
    unsigned long long kp2 = f2pack(k4.z, k4.z), kp3 = f2pack(k4.w, k4.w);
    unsigned long long dp0 = f2pack(d4.x, d4.x), dp1 = f2pack(d4.y, d4.y);
    unsigned long long dp2 = f2pack(d4.z, d4.z), dp3 = f2pack(d4.w, d4.w);

    sp0 = f2mul(sp0, dp0); sp1 = f2mul(sp1, dp1);
    sp2 = f2mul(sp2, dp2); sp3 = f2mul(sp3, dp3);
    float4 nd;
    if (PF) nd = *(const float4*)(db + (U + 1) * 2048);

    unsigned long long acc = f2mul(kp0, sp0);
    acc = f2fma(kp1, sp1, acc);
    acc = f2fma(kp2, sp2, acc);
    acc = f2fma(kp3, sp3, acc);
    acc = red32p(acc);
    float p0 = f2lo(acc), p1 = f2hi(acc);

    float btc = f4c(bt4, U);
    float be0 = btc * (f4c(vA, U) - p0);
    float be1 = btc * (f4c(vB, U) - p1);
    unsigned long long bep = f2pack(be0, be1);

    sp0 = f2fma(bep, kp0, sp0); sp1 = f2fma(bep, kp1, sp1);
    sp2 = f2fma(bep, kp2, sp2); sp3 = f2fma(bep, kp3, sp3);
    float4 nk;
    if (PF) nk = *(const float4*)(kb + (U + 1) * 6144);

    unsigned long long qp0 = f2pack(q4.x, q4.x), qp1 = f2pack(q4.y, q4.y);
    unsigned long long qp2 = f2pack(q4.z, q4.z), qp3 = f2pack(q4.w, q4.w);
    unsigned long long oacc = f2mul(qp0, sp0);
    oacc = f2fma(qp1, sp1, oacc);
    oacc = f2fma(qp2, sp2, oacc);
    oacc = f2fma(qp3, sp3, oacc);
    float4 nq;
    if (PF) nq = *(const float4*)(qb + (U + 1) * 6144);
    oacc = red32p(oacc);

    if (lane < 2) ob[U * 2048 + lane] = (lane ? f2hi(oacc) : f2lo(oacc)) * scale;

    if (PF) { k4 = nk; d4 = nd; q4 = nq; }
}

__global__ void __launch_bounds__(128, 7) kda_scan() {
    int warp = threadIdx.x >> 5, lane = threadIdx.x & 31;
    int bh = blockIdx.x;
    int b = bh >> 4, h = bh & 15;
    int wj = blockIdx.y * 4 + warp;
    int j0 = wj * 2;
    size_t rbase = (size_t)b * T_;

    const float* kb  = g_qkv   + rbase * 6144 + CK + h * 128 + lane * 4;
    const float* qb  = g_qkv   + rbase * 6144 + CQ + h * 128 + lane * 4;
    const float* db  = g_decay + rbase * 2048 + h * 128 + lane * 4;
    const float* v0p = g_vT + (((size_t)bh) * 128 + j0) * 2048;
    const float* v1p = v0p + 2048;
    const float* btp = g_betaT + (size_t)bh * 2048;
    float* ob = g_oscan + rbase * 2048 + h * 128 + j0;

    unsigned long long sp0 = 0ull, sp1 = 0ull, sp2 = 0ull, sp3 = 0ull;
    const float scale = 0.08838834764831845f;

    float4 k4 = *(const float4*)(kb);
    float4 d4 = *(const float4*)(db);
    float4 q4 = *(const float4*)(qb);

    for (int tg = 0; tg < T_ - 4; tg += 4) {
        float4 vA  = *(const float4*)(v0p);
        float4 vB  = *(const float4*)(v1p);
        float4 bt4 = *(const float4*)(btp);
        scan_step<0, 1>(sp0, sp1, sp2, sp3, k4, d4, q4, vA, vB, bt4, kb, qb, db, ob, lane, scale);
        scan_step<1, 1>(sp0, sp1, sp2, sp3, k4, d4, q4, vA, vB, bt4, kb, qb, db, ob, lane, scale);
        scan_step<2, 1>(sp0, sp1, sp2, sp3, k4, d4, q4, vA, vB, bt4, kb, qb, db, ob, lane, scale);
        scan_step<3, 1>(sp0, sp1, sp2, sp3, k4, d4, q4, vA, vB, bt4, kb, qb, db, ob, lane, scale);
        kb += 4 * 6144; qb += 4 * 6144; db += 4 * 2048; ob += 4 * 2048;
        v0p += 4; v1p += 4; btp += 4;
    }
    {
        float4 vA  = *(const float4*)(v0p);
        float4 vB  = *(const float4*)(v1p);
        float4 bt4 = *(const float4*)(btp);
        scan_step<0, 1>(sp0, sp1, sp2, sp3, k4, d4, q4, vA, vB, bt4, kb, qb, db, ob, lane, scale);
        scan_step<1, 1>(sp0, sp1, sp2, sp3, k4, d4, q4, vA, vB, bt4, kb, qb, db, ob, lane, scale);
        scan_step<2, 1>(sp0, sp1, sp2, sp3, k4, d4, q4, vA, vB, bt4, kb, qb, db, ob, lane, scale);
        scan_step<3, 0>(sp0, sp1, sp2, sp3, k4, d4, q4, vA, vB, bt4, kb, qb, db, ob, lane, scale);
    }
}

// ---------------- per-head LayerNorm + sigmoid gate + split to bf16 hi/lo ----------------
__global__ void ln_gate(const float* __restrict__ ln_w, const float* __restrict__ ln_b) {
    int gwarp = (int)(((size_t)blockIdx.x * blockDim.x + threadIdx.x) >> 5);
    int lane = threadIdx.x & 31;
    if (gwarp >= M_ * H_) return;
    int h = gwarp & 15;
    size_t r = (size_t)(gwarp >> 4);

    const float* obp = g_oscan + r * 2048 + h * 128;
    float4 o4 = *(const float4*)(obp + lane * 4);
    float sum = o4.x + o4.y + o4.z + o4.w;
#pragma unroll
    for (int off = 16; off; off >>= 1) sum += __shfl_xor_sync(0xffffffffu, sum, off);
    float mu = sum * (1.f / 128.f);
    float dx = o4.x - mu, dy = o4.y - mu, dz = o4.z - mu, dw = o4.w - mu;
    float sq = dx * dx + dy * dy + dz * dz + dw * dw;
#pragma unroll
    for (int off = 16; off; off >>= 1) sq += __shfl_xor_sync(0xffffffffu, sq, off);
    float rs = rsqrtf(sq * (1.f / 128.f) + 1e-5f);

    float vals[4] = {dx, dy, dz, dw};
#pragma unroll
    for (int e = 0; e < 4; e++) {
        int jj = lane * 4 + e;
        float y = vals[e] * rs * ln_w[jj] + ln_b[jj];
        float gate = sigf(g_P[r * (size_t)NP + CG + h * 128 + jj]);
        y *= gate;
        size_t idx = r * 2048 + h * 128 + jj;
        __nv_bfloat16 hh = __float2bfloat16(y);
        g_yh[idx] = hh;
        g_yl[idx] = __float2bfloat16(y - __bfloat162float(hh));
    }
}

// ---------------- launch ----------------
extern "C" void kernel_launch(void* const* d_in, const int* in_sizes, int n_in,
                              void* d_out, int out_size) {
    const float* x    = (const float*)d_in[0];
    const float* Wq   = (const float*)d_in[1];
    const float* Wk   = (const float*)d_in[2];
    const float* Wv   = (const float*)d_in[3];
    const float* Wa   = (const float*)d_in[4];
    const float* ba   = (const float*)d_in[5];
    const float* Wb   = (const float*)d_in[6];
    const float* bb   = (const float*)d_in[7];
    const float* Wg   = (const float*)d_in[8];
    const float* Wo   = (const float*)d_in[9];
    const float* cqw  = (const float*)d_in[10];
    const float* cqb  = (const float*)d_in[11];
    const float* ckw  = (const float*)d_in[12];
    const float* ckb  = (const float*)d_in[13];
    const float* cvw  = (const float*)d_in[14];
    const float* cvb  = (const float*)d_in[15];
    const float* ln_w = (const float*)d_in[16];
    const float* ln_b = (const float*)d_in[17];
    float* out = (float*)d_out;

    static __nv_bfloat16 *pxh = nullptr, *pxl, *pWh, *pWl, *pyh, *pyl, *pW2h, *pW2l;
    static float *pP;
    static cudaStream_t s1;
    static cudaEvent_t ev0, ev_fork, ev_join;
    if (!pxh) {
        cudaGetSymbolAddress((void**)&pxh, g_xh);
        cudaGetSymbolAddress((void**)&pxl, g_xl);
        cudaGetSymbolAddress((void**)&pWh, g_Wh);
        cudaGetSymbolAddress((void**)&pWl, g_Wl);
        cudaGetSymbolAddress((void**)&pP,  g_P);
        cudaGetSymbolAddress((void**)&pyh, g_yh);
        cudaGetSymbolAddress((void**)&pyl, g_yl);
        cudaGetSymbolAddress((void**)&pW2h, g_W2h);
        cudaGetSymbolAddress((void**)&pW2l, g_W2l);
        cudaFuncSetAttribute(gemm_split, cudaFuncAttributeMaxDynamicSharedMemorySize, 98304);
        cudaStreamCreateWithFlags(&s1, cudaStreamNonBlocking);
        cudaEventCreateWithFlags(&ev0, cudaEventDisableTiming);
        cudaEventCreateWithFlags(&ev_fork, cudaEventDisableTiming);
        cudaEventCreateWithFlags(&ev_join, cudaEventDisableTiming);
    }

    const int TPB = 256;

    // fork side stream early: Wo split has no dependencies
    cudaEventRecord(ev0, 0);
    cudaStreamWaitEvent(s1, ev0, 0);
    split_f32_v4<<<(int)(((size_t)D_ * 2048 / 4 + TPB - 1) / TPB), TPB, 0, s1>>>(
        Wo, pW2h, pW2l, (size_t)D_ * 2048 / 4);

    // main: x split + fused weight build
    split_f32_v4<<<(int)(((size_t)M_ * D_ / 4 + TPB - 1) / TPB), TPB>>>(x, pxh, pxl, (size_t)M_ * D_ / 4);
    build_wcat<<<(int)(((size_t)NP * D_ / 4 + TPB - 1) / TPB), TPB>>>(Wq, Wk, Wv, Wa, Wg, Wb);
    cudaEventRecord(ev_fork, 0);

    // 2a) main: projection GEMM for q|k|v|a|b cols (65 tiles)
    gemm_split<<<dim3(65, M_ / 128), 256, 98304>>>(pxh, pxl, pWh, pWl, pP, M_, NP, D_, 0);
    // 2b) side: g-column GEMM (16 tiles), concurrent with 2a
    cudaStreamWaitEvent(s1, ev_fork, 0);
    gemm_split<<<dim3(16, M_ / 128), 256, 98304, s1>>>(pxh, pxl, pWh, pWl, pP, M_, NP, D_, 65);
    cudaEventRecord(ev_join, s1);

    // 3) fused conv/decay/beta + v-transpose (main stream)
    conv_decay_beta<<<(int)(((size_t)M_ * 2048 + TPB - 1) / TPB), TPB>>>(
        cqw, cqb, ckw, ckb, cvw, cvb, ba, bb);
    transpose_v<<<dim3(64, 4, 64), dim3(32, 8)>>>();

    // 5) gated delta-rule scan
    kda_scan<<<dim3(B_ * H_, 16), 128>>>();

    // join: ln_gate needs the g columns from 2b
    cudaStreamWaitEvent(0, ev_join, 0);

    // 6) LayerNorm + gate + bf16 split
    ln_gate<<<M_ * H_ / 8, 256>>>(ln_w, ln_b);

    // 7) output projection: out = y @ Wo^T   (8192 x 2048 x 2048)
    gemm_split<<<dim3(16, M_ / 128), 256, 98304>>>(pyh, pyl, pW2h, pW2l, out, M_, 2048, D_, 0);
}